// round 9
// baseline (speedup 1.0000x reference)
#include <cuda_runtime.h>
#include <cuda_fp16.h>
#include <math.h>
#include <float.h>

#define NROWS 200000
#define NBAGS 25000
#define DIM   690
#define NREL  53
#define KPAD  704
#define NPAD  64           // P row stride (cols 56..63 unused)
#define NB    56           // computed cols (7 n-tiles)
#define BM    128
#define KC    32
#define NCHUNK 22          // KPAD / KC
#define PF    36           // fp32 A stage pitch (floats)
#define BPITCH 40          // fp16 B pitch (80B rows, LDSM conflict-free)
#define NSTAGE 3
#define A_STAGE_BYTES (BM * PF * 4)            // 18432
#define B_HALF_BYTES  (NB * BPITCH * 2)        // 4480
#define B_STAGE_BYTES (2 * B_HALF_BYTES)       // 8960 (hi then lo)
#define SMEM_B_OFF    (NSTAGE * A_STAGE_BYTES) // 55296
#define SMEM_TOTAL    (SMEM_B_OFF + NSTAGE * B_STAGE_BYTES)  // 82176
#define WCAP  128

// ---------------- scratch (device globals: allocation-free) ----------------
__device__ __align__(16) float g_P[(size_t)NROWS * NPAD];       // 51.2 MB
__device__ float g_wglob[NROWS];

// ---------------- PTX helpers ----------------
__device__ __forceinline__ void mma_f16(float* c, const unsigned* a, const unsigned* b) {
    asm volatile(
        "mma.sync.aligned.m16n8k16.row.col.f32.f16.f16.f32 "
        "{%0,%1,%2,%3}, {%4,%5,%6,%7}, {%8,%9}, {%0,%1,%2,%3};"
        : "+f"(c[0]), "+f"(c[1]), "+f"(c[2]), "+f"(c[3])
        : "r"(a[0]), "r"(a[1]), "r"(a[2]), "r"(a[3]), "r"(b[0]), "r"(b[1]));
}
__device__ __forceinline__ void ldsm2(unsigned* r, unsigned addr) {
    asm volatile("ldmatrix.sync.aligned.m8n8.x2.shared.b16 {%0,%1}, [%2];"
                 : "=r"(r[0]), "=r"(r[1]) : "r"(addr));
}
__device__ __forceinline__ void cp8(unsigned dst, const void* src, int bytes) {
    asm volatile("cp.async.ca.shared.global [%0], [%1], 8, %2;"
                 :: "r"(dst), "l"(src), "r"(bytes));
}
__device__ __forceinline__ void cp_commit() {
    asm volatile("cp.async.commit_group;" ::: "memory");
}
__device__ __forceinline__ void cp_wait1() {
    asm volatile("cp.async.wait_group 1;" ::: "memory");
}
__device__ __forceinline__ void sts128(unsigned a, unsigned x, unsigned y,
                                       unsigned z, unsigned w) {
    asm volatile("st.shared.v4.b32 [%0], {%1,%2,%3,%4};"
                 :: "r"(a), "r"(x), "r"(y), "r"(z), "r"(w) : "memory");
}

// ---------------- K1: P = repre @ rel^T, pipelined fp16 2-term MMA ---------
// B (rel) staged per-chunk from L2 with inline fp16 hi/lo split.
__global__ __launch_bounds__(256) void k_pgemm(const float* __restrict__ repre,
                                               const float* __restrict__ rel) {
    extern __shared__ __align__(16) char smem[];
    unsigned sbase = (unsigned)__cvta_generic_to_shared(smem);
    float* sF = (float*)smem;

    int row0 = blockIdx.x * BM;
    int tid = threadIdx.x, wid = tid >> 5, lane = tid & 31;

    // ---- A cp geometry ----
    int ar  = tid >> 1;
    int asb = (tid & 1) * 8;
    int gr  = row0 + ar;
    bool arow_ok = gr < NROWS;
    const float* asrc_row = repre + (size_t)(arow_ok ? gr : (NROWS - 1)) * DIM;
    unsigned adst_row = sbase + (unsigned)(ar * PF * 4);

    // ---- B stage geometry: 224 threads cover 56 rows x 4 slots of 8 floats ----
    int bn = tid >> 2, bs = tid & 3;
    bool b_ok = (tid < NB * 4) && (bn < NREL);       // rows 53..55 stay zero
    const float* bsrc = rel + (size_t)(b_ok ? bn : 0) * DIM;
    unsigned bso = (unsigned)((bn * BPITCH + bs * 8) * 2);

    // ---- compute geometry ----
    int wrow = wid * 16;
    int g = lane >> 2, th = lane & 3;
    int brow = lane & 7, bcolsel = lane & 8;

    float acc[7][4];
#pragma unroll
    for (int j = 0; j < 7; j++)
#pragma unroll
        for (int q = 0; q < 4; q++) acc[j][q] = 0.f;

    auto issueA = [&](int cs) {
        int st = cs % NSTAGE;
        int k0 = cs * KC;
        unsigned da = adst_row + (unsigned)(st * A_STAGE_BYTES) + (unsigned)(asb * 8);
#pragma unroll
        for (int i = 0; i < 8; i++) {
            int kf = k0 + (asb + i) * 2;
            int bytes = arow_ok ? max(0, min(8, (DIM - kf) * 4)) : 0;
            const float* sp = asrc_row + (bytes > 0 ? kf : 0);
            cp8(da + i * 8, sp, bytes);
        }
    };

    // zero B smem once (covers zero-padded rows/cols for all stages)
    for (int t = tid; t < NSTAGE * B_STAGE_BYTES / 4; t += 256)
        ((unsigned*)(smem + SMEM_B_OFF))[t] = 0u;

    issueA(0); cp_commit();
    issueA(1); cp_commit();
    __syncthreads();    // B zeros visible

    for (int c = 0; c < NCHUNK; c++) {
        int st = c % NSTAGE;
        int k0 = c * KC;

        // ---- B LDG for this chunk (early; L2-hot) ----
        float2 bvv[4];
#pragma unroll
        for (int i = 0; i < 4; i++) {
            int kg = k0 + bs * 8 + i * 2;
            float2 t = make_float2(0.f, 0.f);
            if (b_ok) {
                if (kg + 1 < DIM) t = *(const float2*)(bsrc + kg);
                else if (kg < DIM) t.x = bsrc[kg];
            }
            bvv[i] = t;
        }

        cp_wait1();
        __syncthreads();
        const float* A = sF + st * (BM * PF);
        unsigned sBst = sbase + SMEM_B_OFF + (unsigned)(st * B_STAGE_BYTES);

        // ---- build fp16 A fragments in regs (both k16 steps) ----
        unsigned ah[2][4];
#pragma unroll
        for (int ks2 = 0; ks2 < 2; ks2++) {
#pragma unroll
            for (int q = 0; q < 4; q++) {
                int r   = wrow + g + (q & 1) * 8;
                int col = ks2 * 16 + th * 2 + (q >> 1) * 8;
                float2 v = *(const float2*)(A + r * PF + col);
                asm("cvt.rn.f16x2.f32 %0, %1, %2;"
                    : "=r"(ah[ks2][q]) : "f"(v.y), "f"(v.x));
            }
        }

        // ---- B convert + STS (hi + residual lo) ----
        if (tid < NB * 4) {
            unsigned h[4], l[4];
#pragma unroll
            for (int i = 0; i < 4; i++) {
                float2 t = bvv[i];
                __half hx = __float2half(t.x), hy = __float2half(t.y);
                float lx = t.x - __half2float(hx);
                float ly = t.y - __half2float(hy);
                __half2 hp = __halves2half2(hx, hy);
                h[i] = *(unsigned*)&hp;
                asm("cvt.rn.f16x2.f32 %0, %1, %2;" : "=r"(l[i]) : "f"(ly), "f"(lx));
            }
            sts128(sBst + bso, h[0], h[1], h[2], h[3]);
            sts128(sBst + B_HALF_BYTES + bso, l[0], l[1], l[2], l[3]);
        }
        __syncthreads();

        // ---- MMA over 7 n-tiles x 2 k-steps x 2 terms ----
#pragma unroll
        for (int j = 0; j < 7; j++) {
            unsigned bb = sBst + (unsigned)(((j * 8 + brow) * BPITCH + bcolsel) * 2);
#pragma unroll
            for (int ks2 = 0; ks2 < 2; ks2++) {
                unsigned bhi[2], blo[2];
                ldsm2(bhi, bb + ks2 * 32);
                ldsm2(blo, bb + B_HALF_BYTES + ks2 * 32);
                mma_f16(acc[j], ah[ks2], bhi);
                mma_f16(acc[j], ah[ks2], blo);
            }
        }
        if (c + 2 < NCHUNK) issueA(c + 2);
        cp_commit();
    }

    // ---- epilogue: write P (56 cols) ----
    int r1 = row0 + wrow + g;
    int r2 = r1 + 8;
#pragma unroll
    for (int j = 0; j < 7; j++) {
        int col = j * 8 + th * 2;
        if (r1 < NROWS)
            *(float2*)&g_P[(size_t)r1 * NPAD + col] = make_float2(acc[j][0], acc[j][1]);
        if (r2 < NROWS)
            *(float2*)&g_P[(size_t)r2 * NPAD + col] = make_float2(acc[j][2], acc[j][3]);
    }
}

// ---------------- K2: per-bag softmax + combine over P ---------------------
__global__ __launch_bounds__(256) void k_bags(const int* __restrict__ scope,
                                              const int* __restrict__ labels,
                                              const float* __restrict__ bias,
                                              float* __restrict__ out) {
    __shared__ float wbuf[8][WCAP];
    int wid = threadIdx.x >> 5, lane = threadIdx.x & 31;
    int bag = blockIdx.x * 8 + wid;
    if (bag >= NBAGS) return;
    int s = scope[2 * bag];
    int e = scope[2 * bag + 1];
    int c = e - s;
    float* w = (c <= WCAP) ? wbuf[wid] : (g_wglob + s);

    float m = -FLT_MAX;
    for (int i = lane; i < c; i += 32) {
        int gi = s + i;
        float lg = g_P[(size_t)gi * NPAD + labels[gi]];
        w[i] = lg;
        m = fmaxf(m, lg);
    }
#pragma unroll
    for (int o = 16; o; o >>= 1) m = fmaxf(m, __shfl_xor_sync(0xffffffffu, m, o));

    float sum = 0.f;
    for (int i = lane; i < c; i += 32) {
        float ev = __expf(w[i] - m);
        w[i] = ev;
        sum += ev;
    }
#pragma unroll
    for (int o = 16; o; o >>= 1) sum += __shfl_xor_sync(0xffffffffu, sum, o);
    float inv = 1.f / sum;
    __syncwarp();

    int col = lane * 2;
    float2 o2 = make_float2(0.f, 0.f);
    const float* pbase = g_P + (size_t)s * NPAD + col;
#pragma unroll 8
    for (int i = 0; i < c; i++) {
        float wi = w[i] * inv;
        float2 p2 = *(const float2*)(pbase + (size_t)i * NPAD);
        o2.x = fmaf(wi, p2.x, o2.x);
        o2.y = fmaf(wi, p2.y, o2.y);
    }
    if (col < NREL)     out[(size_t)bag * NREL + col]     = o2.x + bias[col];
    if (col + 1 < NREL) out[(size_t)bag * NREL + col + 1] = o2.y + bias[col + 1];
}

// ---------------- launch ----------------
extern "C" void kernel_launch(void* const* d_in, const int* in_sizes, int n_in,
                              void* d_out, int out_size) {
    const float* repre  = (const float*)d_in[0];   // [N, D]
    const float* rel    = (const float*)d_in[1];   // [R, D]
    const float* bias   = (const float*)d_in[2];   // [R]
    const int* scope    = (const int*)d_in[3];     // [NBAGS, 2] int32
    const int* labels   = (const int*)d_in[4];     // [N]        int32
    float* out = (float*)d_out;                    // [NBAGS, R]

    (void)in_sizes; (void)n_in; (void)out_size;

    cudaFuncSetAttribute(k_pgemm, cudaFuncAttributeMaxDynamicSharedMemorySize,
                         SMEM_TOTAL);

    k_pgemm<<<(NROWS + BM - 1) / BM, 256, SMEM_TOTAL>>>(repre, rel);
    k_bags<<<(NBAGS + 7) / 8, 256>>>(scope, labels, bias, out);
}

// round 11
// speedup vs baseline: 1.4127x; 1.4127x over previous
#include <cuda_runtime.h>
#include <cuda_fp16.h>
#include <math.h>
#include <float.h>

#define NROWS 200000
#define NBAGS 25000
#define DIM   690
#define NREL  53
#define NPAD  64           // P row stride (cols 56..63 unused)
#define NKS   44           // k16 steps (704 / 16)
#define NJ    7            // n-tiles (56 cols)
#define WCAP  128

// ---------------- scratch (device globals: allocation-free) ----------------
__device__ __align__(16) float g_P[(size_t)NROWS * NPAD];       // 51.2 MB
__device__ __align__(16) uint4 g_Bpack[NKS * NJ * 32];          // 158 KB frag table
__device__ float g_wglob[NROWS];

// ---------------- PTX helpers ----------------
__device__ __forceinline__ void mma_f16(float* c, const unsigned* a, const unsigned* b) {
    asm volatile(
        "mma.sync.aligned.m16n8k16.row.col.f32.f16.f16.f32 "
        "{%0,%1,%2,%3}, {%4,%5,%6,%7}, {%8,%9}, {%0,%1,%2,%3};"
        : "+f"(c[0]), "+f"(c[1]), "+f"(c[2]), "+f"(c[3])
        : "r"(a[0]), "r"(a[1]), "r"(a[2]), "r"(a[3]), "r"(b[0]), "r"(b[1]));
}
__device__ __forceinline__ unsigned packh2(float x, float y) {
    unsigned r;
    asm("cvt.rn.f16x2.f32 %0, %1, %2;" : "=r"(r) : "f"(y), "f"(x));
    return r;
}

// ---------------- K0: pack B = rel into per-lane MMA fragment table --------
// entry (ks, j, lane): n = j*8 + (lane>>2), k = ks*16 + (lane&3)*2
//   .x = hi(B[k],B[k+1])  .y = hi(B[k+8],B[k+9])  .z/.w = fp16 residuals
__global__ void k_prep(const float* __restrict__ rel) {
    int idx = blockIdx.x * blockDim.x + threadIdx.x;
    if (idx >= NKS * NJ * 32) return;
    int ks = idx / (NJ * 32), rem = idx % (NJ * 32);
    int j = rem / 32, lane = rem % 32;
    int n = j * 8 + (lane >> 2);
    int k = ks * 16 + (lane & 3) * 2;
    float v[4] = {0.f, 0.f, 0.f, 0.f};
    if (n < NREL) {
        if (k < DIM)     v[0] = rel[n * DIM + k];
        if (k + 1 < DIM) v[1] = rel[n * DIM + k + 1];
        if (k + 8 < DIM) v[2] = rel[n * DIM + k + 8];
        if (k + 9 < DIM) v[3] = rel[n * DIM + k + 9];
    }
    float h[4], l[4];
#pragma unroll
    for (int i = 0; i < 4; i++) {
        h[i] = __half2float(__float2half(v[i]));
        l[i] = v[i] - h[i];
    }
    uint4 o;
    o.x = packh2(h[0], h[1]);
    o.y = packh2(h[2], h[3]);
    o.z = packh2(l[0], l[1]);
    o.w = packh2(l[2], l[3]);
    g_Bpack[idx] = o;
}

// ---------------- K1: P = repre @ rel^T — barrier-free, smem-free ----------
// one warp per 16-row strip; A frags LDG'd direct, B frags from g_Bpack
__global__ __launch_bounds__(256) void k_pgemm(const float* __restrict__ repre) {
    int wid = threadIdx.x >> 5, lane = threadIdx.x & 31;
    int w = blockIdx.x * 8 + wid;          // global warp = strip index
    int row0 = w * 16;
    if (row0 >= NROWS) return;
    int g = lane >> 2, th = lane & 3;
    int r0 = row0 + g, r1 = r0 + 8;
    bool ok0 = r0 < NROWS, ok1 = r1 < NROWS;
    const float* p0 = repre + (size_t)(ok0 ? r0 : 0) * DIM;
    const float* p1 = repre + (size_t)(ok1 ? r1 : 0) * DIM;

    float acc[NJ][4];
#pragma unroll
    for (int j = 0; j < NJ; j++)
#pragma unroll
        for (int q = 0; q < 4; q++) acc[j][q] = 0.f;

    const uint4* bp_lane = g_Bpack + lane;

#pragma unroll 2
    for (int ks = 0; ks < NKS; ks++) {
        int c0 = ks * 16 + th * 2;
        int c1 = c0 + 8;
        // A fragment: 4x LDG.64 (independent)
        float2 v0 = (ok0 && c0 < DIM) ? *(const float2*)(p0 + c0) : make_float2(0.f, 0.f);
        float2 v1 = (ok1 && c0 < DIM) ? *(const float2*)(p1 + c0) : make_float2(0.f, 0.f);
        float2 v2 = (ok0 && c1 < DIM) ? *(const float2*)(p0 + c1) : make_float2(0.f, 0.f);
        float2 v3 = (ok1 && c1 < DIM) ? *(const float2*)(p1 + c1) : make_float2(0.f, 0.f);
        unsigned a[4];
        a[0] = packh2(v0.x, v0.y);
        a[1] = packh2(v1.x, v1.y);
        a[2] = packh2(v2.x, v2.y);
        a[3] = packh2(v3.x, v3.y);

        const uint4* bp = bp_lane + (size_t)ks * NJ * 32;
#pragma unroll
        for (int j = 0; j < NJ; j++) {
            uint4 b = bp[j * 32];
            unsigned bhi[2] = {b.x, b.y};
            unsigned blo[2] = {b.z, b.w};
            mma_f16(acc[j], a, bhi);
            mma_f16(acc[j], a, blo);
        }
    }

    // epilogue: write P (56 cols, rows r0 / r1)
#pragma unroll
    for (int j = 0; j < NJ; j++) {
        int col = j * 8 + th * 2;
        if (ok0)
            *(float2*)&g_P[(size_t)r0 * NPAD + col] = make_float2(acc[j][0], acc[j][1]);
        if (ok1)
            *(float2*)&g_P[(size_t)r1 * NPAD + col] = make_float2(acc[j][2], acc[j][3]);
    }
}

// ---------------- K2: per-bag softmax + combine over P ---------------------
__global__ __launch_bounds__(256) void k_bags(const int* __restrict__ scope,
                                              const int* __restrict__ labels,
                                              const float* __restrict__ bias,
                                              float* __restrict__ out) {
    __shared__ float wbuf[8][WCAP];
    int wid = threadIdx.x >> 5, lane = threadIdx.x & 31;
    int bag = blockIdx.x * 8 + wid;
    if (bag >= NBAGS) return;
    int s = scope[2 * bag];
    int e = scope[2 * bag + 1];
    int c = e - s;
    float* w = (c <= WCAP) ? wbuf[wid] : (g_wglob + s);

    float m = -FLT_MAX;
    for (int i = lane; i < c; i += 32) {
        int gi = s + i;
        float lg = g_P[(size_t)gi * NPAD + labels[gi]];
        w[i] = lg;
        m = fmaxf(m, lg);
    }
#pragma unroll
    for (int o = 16; o; o >>= 1) m = fmaxf(m, __shfl_xor_sync(0xffffffffu, m, o));

    float sum = 0.f;
    for (int i = lane; i < c; i += 32) {
        float ev = __expf(w[i] - m);
        w[i] = ev;
        sum += ev;
    }
#pragma unroll
    for (int o = 16; o; o >>= 1) sum += __shfl_xor_sync(0xffffffffu, sum, o);
    float inv = 1.f / sum;
    __syncwarp();

    int col = lane * 2;
    float2 o2 = make_float2(0.f, 0.f);
    const float* pbase = g_P + (size_t)s * NPAD + col;
#pragma unroll 8
    for (int i = 0; i < c; i++) {
        float wi = w[i] * inv;
        float2 p2 = *(const float2*)(pbase + (size_t)i * NPAD);
        o2.x = fmaf(wi, p2.x, o2.x);
        o2.y = fmaf(wi, p2.y, o2.y);
    }
    if (col < NREL)     out[(size_t)bag * NREL + col]     = o2.x + bias[col];
    if (col + 1 < NREL) out[(size_t)bag * NREL + col + 1] = o2.y + bias[col + 1];
}

// ---------------- launch ----------------
extern "C" void kernel_launch(void* const* d_in, const int* in_sizes, int n_in,
                              void* d_out, int out_size) {
    const float* repre  = (const float*)d_in[0];   // [N, D]
    const float* rel    = (const float*)d_in[1];   // [R, D]
    const float* bias   = (const float*)d_in[2];   // [R]
    const int* scope    = (const int*)d_in[3];     // [NBAGS, 2] int32
    const int* labels   = (const int*)d_in[4];     // [N]        int32
    float* out = (float*)d_out;                    // [NBAGS, R]

    (void)in_sizes; (void)n_in; (void)out_size;

    k_prep<<<(NKS * NJ * 32 + 255) / 256, 256>>>(rel);
    int nwarps = (NROWS + 15) / 16;                 // 12500 strips
    k_pgemm<<<(nwarps + 7) / 8, 256>>>(repre);
    k_bags<<<(NBAGS + 7) / 8, 256>>>(scope, labels, bias, out);
}